// round 12
// baseline (speedup 1.0000x reference)
#include <cuda_runtime.h>

#define BB 64
#define NN 2048
#define DIM 768
#define D4 (DIM / 4)             // 192 float4 per row
#define POOL 1024
#define PLEN 16
#define ROWS 128                 // rows per copy/mean block
#define CHUNKS (NN / ROWS)       // 16 partial chunks per batch
#define OUTROWS (2 * PLEN + NN)  // 2080
#define KPB 8                    // keys per sim block
#define NBLK (POOL / KPB)        // 128 sim blocks
#define EPS 1e-12f

// Static device scratch — referenced ONLY from device code. Zero-initialized
// at module load; ticket counters self-reset so graph replays see 0.
__device__ float4 g_partial[BB * CHUNKS * D4];   // 3.1 MB chunked row-sums
__device__ float4 g_xnorm[BB * D4];
__device__ float4 g_res[BB * D4];
__device__ float2 g_part1[BB * NBLK];            // (val, idx-bits) partial argmax
__device__ float2 g_part2[BB * NBLK];
__device__ float  g_m1[BB];
__device__ float  g_m2[BB];
__device__ int    g_idx1[BB];
__device__ int    g_idx2[BB];
__device__ unsigned int g_cntA;                  // sim pass-0 ticket
__device__ unsigned int g_cntB;                  // sim pass-1 ticket

// ---------------------------------------------------------------------------
// K1: stream x_embed -> out rows [32,2080) via float4, accumulating per-chunk
// column sums. grid = BB*CHUNKS (1024), block = 192. NO fences (R9 version).
// ---------------------------------------------------------------------------
__global__ __launch_bounds__(D4) void copy_mean_kernel(
    const float4* __restrict__ x, float4* __restrict__ out)
{
    int blk = blockIdx.x;
    int b = blk / CHUNKS;
    int k = blk % CHUNKS;
    int c = threadIdx.x;

    const float4* src = x   + ((size_t)b * NN + (size_t)k * ROWS) * D4 + c;
    float4*       dst = out + ((size_t)b * OUTROWS + 2 * PLEN + (size_t)k * ROWS) * D4 + c;

    float4 s = make_float4(0.f, 0.f, 0.f, 0.f);
    #pragma unroll 8
    for (int r = 0; r < ROWS; r++) {
        float4 v = src[(size_t)r * D4];
        s.x += v.x; s.y += v.y; s.z += v.z; s.w += v.w;
        dst[(size_t)r * D4] = v;
    }
    g_partial[((size_t)b * CHUNKS + k) * D4 + c] = s;
}

// ---------------------------------------------------------------------------
// K2: reduce chunked partials -> mean -> x_norm. grid = BB, block = 192.
// ---------------------------------------------------------------------------
__global__ __launch_bounds__(D4) void xnorm_kernel()
{
    int b = blockIdx.x;
    int c = threadIdx.x;

    float4 s = make_float4(0.f, 0.f, 0.f, 0.f);
    #pragma unroll
    for (int k = 0; k < CHUNKS; k++) {
        float4 v = g_partial[((size_t)b * CHUNKS + k) * D4 + c];
        s.x += v.x; s.y += v.y; s.z += v.z; s.w += v.w;
    }
    const float inv_n = 1.0f / NN;
    float4 m = make_float4(s.x * inv_n, s.y * inv_n, s.z * inv_n, s.w * inv_n);

    __shared__ float red[D4];
    red[c] = m.x * m.x + m.y * m.y + m.z * m.z + m.w * m.w;
    __syncthreads();
    if (c < 64) red[c] += red[c + 64] + red[c + 128];
    __syncthreads();
    for (int o = 32; o >= 1; o >>= 1) {
        if (c < o) red[c] += red[c + o];
        __syncthreads();
    }
    float inv = rsqrtf(fmaxf(red[0], EPS));
    g_xnorm[(size_t)b * D4 + c] = make_float4(m.x * inv, m.y * inv, m.z * inv, m.w * inv);
}

// ---------------------------------------------------------------------------
// Tail for the last sim block: final argmax over partials for all 64 batches,
// plus (pass 0) the residual. __noinline__ + unroll 1 keeps its register
// pressure out of the sim hot loop. Runs once per pass — speed irrelevant.
// ---------------------------------------------------------------------------
__device__ __noinline__ void sim_tail(const float4* __restrict__ pkey, int pass,
                                      int tid, int lane, int w)
{
    __shared__ int s_id[BB];
    const float2* part = (pass == 0) ? g_part1 : g_part2;

    #pragma unroll 1
    for (int bi = 0; bi < 8; bi++) {
        int b = w * 8 + bi;
        float best = -1e30f; int bp = 0x7fffffff;
        #pragma unroll 1
        for (int j = 0; j < NBLK / 32; j++) {        // ascending block index
            float2 pr = part[(size_t)b * NBLK + lane + j * 32];
            float v = pr.x; int p = __float_as_int(pr.y);
            if (v > best || (v == best && p < bp)) { best = v; bp = p; }
        }
        #pragma unroll
        for (int o = 16; o; o >>= 1) {
            float v = __shfl_xor_sync(0xffffffffu, best, o);
            int   p = __shfl_xor_sync(0xffffffffu, bp, o);
            if (v > best || (v == best && p < bp)) { best = v; bp = p; }
        }
        if (lane == 0) {
            s_id[b] = bp;
            if (pass == 0) { g_idx1[b] = bp; g_m1[b] = best; }
            else           { g_idx2[b] = bp; g_m2[b] = best; }
        }
    }
    __syncthreads();

    if (pass == 0) {
        // residual = prompt_key[idx1] - x_norm, all 64 batches
        #pragma unroll 1
        for (int bi = 0; bi < 8; bi++) {
            int b = w * 8 + bi;
            int id = s_id[b];
            #pragma unroll 1
            for (int j = 0; j < 6; j++) {
                int c = lane + j * 32;
                float4 kv = pkey[(size_t)id * D4 + c];
                float4 xv = g_xnorm[(size_t)b * D4 + c];
                g_res[(size_t)b * D4 + c] =
                    make_float4(kv.x - xv.x, kv.y - xv.y, kv.z - xv.z, kv.w - xv.w);
            }
        }
    }

    if (tid == 0) { if (pass == 0) g_cntA = 0u; else g_cntB = 0u; }
}

// ---------------------------------------------------------------------------
// K3/K4: similarity + per-block partial argmax; last block (ticket) runs the
// tail. grid = NBLK (128), block = 256 (8 warps x 8 batches).
// launch_bounds(256,2) caps regs at 128 so the hot loop never spills.
// ---------------------------------------------------------------------------
__global__ __launch_bounds__(256, 2) void sim_kernel(
    const float4* __restrict__ keys, const float4* __restrict__ pkey, int pass)
{
    int blk = blockIdx.x;
    int tid = threadIdx.x;
    int lane = tid & 31;
    int w = tid >> 5;

    __shared__ float4 kk[KPB][D4];     // 24 KB
    __shared__ float  inv[KPB];

    for (int i = tid; i < KPB * D4; i += 256) {
        int kr = i / D4, cc = i % D4;
        kk[kr][cc] = keys[((size_t)blk * KPB + kr) * D4 + cc];
    }
    __syncthreads();

    // warp w: inverse norm of key w
    {
        float s = 0.f;
        #pragma unroll
        for (int j = 0; j < 6; j++) {
            float4 v = kk[w][lane + j * 32];
            s += v.x * v.x + v.y * v.y + v.z * v.z + v.w * v.w;
        }
        #pragma unroll
        for (int o = 16; o; o >>= 1) s += __shfl_xor_sync(0xffffffffu, s, o);
        if (lane == 0) inv[w] = rsqrtf(fmaxf(s, EPS));
    }
    __syncthreads();

    const float4* xbase = (pass == 0) ? g_xnorm : g_res;
    float2* part = (pass == 0) ? g_part1 : g_part2;

    #pragma unroll
    for (int bi = 0; bi < 8; bi++) {
        int b = w * 8 + bi;
        const float4* xr = xbase + (size_t)b * D4;
        float4 q[6];
        #pragma unroll
        for (int j = 0; j < 6; j++) q[j] = xr[lane + j * 32];

        float best = -1e30f; int bp = 0;
        #pragma unroll
        for (int kr = 0; kr < KPB; kr++) {
            float s = 0.f;
            #pragma unroll
            for (int j = 0; j < 6; j++) {
                float4 k = kk[kr][lane + j * 32];
                s += q[j].x * k.x + q[j].y * k.y + q[j].z * k.z + q[j].w * k.w;
            }
            #pragma unroll
            for (int o = 16; o; o >>= 1) s += __shfl_xor_sync(0xffffffffu, s, o);
            s *= inv[kr];
            if (s > best) { best = s; bp = blk * KPB + kr; }  // ascending -> lowest idx
        }
        if (lane == 0) {
            float2 pr; pr.x = best; pr.y = __int_as_float(bp);
            part[(size_t)b * NBLK + blk] = pr;
        }
    }

    // ---- ticket: last sim block runs the tail (tiny store footprint) ----
    __threadfence();
    __syncthreads();
    __shared__ unsigned int s_tick;
    if (tid == 0) s_tick = atomicAdd(pass == 0 ? &g_cntA : &g_cntB, 1u);
    __syncthreads();
    if (s_tick != NBLK - 1) return;
    __threadfence();   // acquire: peers' partials visible

    sim_tail(pkey, pass, tid, lane, w);
}

// ---------------------------------------------------------------------------
// K5: gather selected prompt tiles into out rows [0,32) + write scalar.
// grid = BB*4 (256 blocks, 4 per batch), block = 256.
// ---------------------------------------------------------------------------
__global__ __launch_bounds__(256) void gather_kernel(
    const float4* __restrict__ prompt, const float4* __restrict__ rprompt,
    float4* __restrict__ out, int write_scalar, size_t scalar_off)
{
    int b = blockIdx.x >> 2;
    int q = blockIdx.x & 3;
    int tid = threadIdx.x;

    const int TOT = PLEN * D4;                 // 3072 float4 per tile
    const float4* src1 = rprompt + (size_t)g_idx2[b] * TOT;  // rows 0..15
    const float4* src2 = prompt  + (size_t)g_idx1[b] * TOT;  // rows 16..31
    float4* dst = out + (size_t)b * OUTROWS * D4;

    const int QUARTER = (2 * TOT) / 4;         // 1536
    int base = q * QUARTER;
    #pragma unroll
    for (int j = 0; j < QUARTER / 256; j++) {  // 6 iterations
        int i = base + tid + j * 256;
        float4 v = (i < TOT) ? src1[i] : src2[i - TOT];
        dst[i] = v;
    }

    if (write_scalar && blockIdx.x == 0 && tid == 0) {
        float total = 0.f;
        #pragma unroll
        for (int bb = 0; bb < BB; bb++) total += g_m1[bb] + g_m2[bb];
        ((float*)out)[scalar_off] = total * (1.0f / BB);
    }
}

// ---------------------------------------------------------------------------
extern "C" void kernel_launch(void* const* d_in, const int* in_sizes, int n_in,
                              void* d_out, int out_size)
{
    const float4* x       = (const float4*)d_in[0];
    const float4* prompt  = (const float4*)d_in[1];
    const float4* pkey4   = (const float4*)d_in[2];
    const float4* rprompt = (const float4*)d_in[3];
    const float4* rkey4   = (const float4*)d_in[4];
    float4* out = (float4*)d_out;

    copy_mean_kernel<<<BB * CHUNKS, D4>>>(x, out);
    xnorm_kernel<<<BB, D4>>>();
    sim_kernel<<<NBLK, 256>>>(pkey4, pkey4, 0);
    sim_kernel<<<NBLK, 256>>>(rkey4, pkey4, 1);

    long long prompted_elems = (long long)BB * OUTROWS * DIM;  // 102,236,160
    int write_scalar = ((long long)out_size > prompted_elems) ? 1 : 0;
    gather_kernel<<<BB * 4, 256>>>(prompt, rprompt, out, write_scalar,
                                   (size_t)prompted_elems);
}

// round 13
// speedup vs baseline: 1.2916x; 1.2916x over previous
#include <cuda_runtime.h>

#define BB 64
#define NN 2048
#define DIM 768
#define D4 (DIM / 4)             // 192 float4 per row
#define POOL 1024
#define PLEN 16
#define ROWS 128                 // rows per copy/mean block
#define CHUNKS (NN / ROWS)       // 16 partial chunks per batch
#define OUTROWS (2 * PLEN + NN)  // 2080
#define KPB 8                    // keys per sim block
#define NBLK (POOL / KPB)        // 128 key-blocks
#define EPS 1e-12f

// Static device scratch — referenced ONLY from device code.
__device__ float4 g_partial[BB * CHUNKS * D4];   // 3.1 MB chunked row-sums
__device__ float4 g_xnorm[BB * D4];
__device__ float4 g_res[BB * D4];
__device__ float2 g_part1[BB * NBLK];            // (val, idx-bits) partial argmax
__device__ float2 g_part2[BB * NBLK];
__device__ float  g_m1[BB];
__device__ int    g_idx1[BB];

// ---------------------------------------------------------------------------
// K1: stream x_embed -> out rows [32,2080) via float4, accumulating per-chunk
// column sums. grid = BB*CHUNKS (1024), block = 192. (R9 version, no fences.)
// ---------------------------------------------------------------------------
__global__ __launch_bounds__(D4) void copy_mean_kernel(
    const float4* __restrict__ x, float4* __restrict__ out)
{
    int blk = blockIdx.x;
    int b = blk / CHUNKS;
    int k = blk % CHUNKS;
    int c = threadIdx.x;

    const float4* src = x   + ((size_t)b * NN + (size_t)k * ROWS) * D4 + c;
    float4*       dst = out + ((size_t)b * OUTROWS + 2 * PLEN + (size_t)k * ROWS) * D4 + c;

    float4 s = make_float4(0.f, 0.f, 0.f, 0.f);
    #pragma unroll 8
    for (int r = 0; r < ROWS; r++) {
        float4 v = src[(size_t)r * D4];
        s.x += v.x; s.y += v.y; s.z += v.z; s.w += v.w;
        dst[(size_t)r * D4] = v;
    }
    g_partial[((size_t)b * CHUNKS + k) * D4 + c] = s;
}

// ---------------------------------------------------------------------------
// K2: reduce chunked partials -> mean -> x_norm. grid = BB, block = 192.
// ---------------------------------------------------------------------------
__global__ __launch_bounds__(D4) void xnorm_kernel()
{
    int b = blockIdx.x;
    int c = threadIdx.x;

    float4 s = make_float4(0.f, 0.f, 0.f, 0.f);
    #pragma unroll
    for (int k = 0; k < CHUNKS; k++) {
        float4 v = g_partial[((size_t)b * CHUNKS + k) * D4 + c];
        s.x += v.x; s.y += v.y; s.z += v.z; s.w += v.w;
    }
    const float inv_n = 1.0f / NN;
    float4 m = make_float4(s.x * inv_n, s.y * inv_n, s.z * inv_n, s.w * inv_n);

    __shared__ float red[D4];
    red[c] = m.x * m.x + m.y * m.y + m.z * m.z + m.w * m.w;
    __syncthreads();
    if (c < 64) red[c] += red[c + 64] + red[c + 128];
    __syncthreads();
    for (int o = 32; o >= 1; o >>= 1) {
        if (c < o) red[c] += red[c + o];
        __syncthreads();
    }
    float inv = rsqrtf(fmaxf(red[0], EPS));
    g_xnorm[(size_t)b * D4 + c] = make_float4(m.x * inv, m.y * inv, m.z * inv, m.w * inv);
}

// ---------------------------------------------------------------------------
// K3/K5: similarity + per-block partial argmax. grid = 2*NBLK (256),
// block = 256 (8 warps). Block owns key-block kb = blockIdx>>1 (8 keys in
// smem) and batch-half bh = blockIdx&1; each warp handles 4 batches.
// pass=0: queries=g_xnorm -> g_part1;  pass=1: queries=g_res -> g_part2.
// NO tail fusion (R11/R12 showed it spills the hot loop).
// ---------------------------------------------------------------------------
__global__ __launch_bounds__(256) void sim_kernel(
    const float4* __restrict__ keys, int pass)
{
    int kb = blockIdx.x >> 1;
    int bh = blockIdx.x & 1;
    int tid = threadIdx.x;
    int lane = tid & 31;
    int w = tid >> 5;

    __shared__ float4 kk[KPB][D4];     // 24 KB
    __shared__ float  inv[KPB];

    for (int i = tid; i < KPB * D4; i += 256) {
        int kr = i / D4, cc = i % D4;
        kk[kr][cc] = keys[((size_t)kb * KPB + kr) * D4 + cc];
    }
    __syncthreads();

    // warp w: inverse norm of key w
    {
        float s = 0.f;
        #pragma unroll
        for (int j = 0; j < 6; j++) {
            float4 v = kk[w][lane + j * 32];
            s += v.x * v.x + v.y * v.y + v.z * v.z + v.w * v.w;
        }
        #pragma unroll
        for (int o = 16; o; o >>= 1) s += __shfl_xor_sync(0xffffffffu, s, o);
        if (lane == 0) inv[w] = rsqrtf(fmaxf(s, EPS));
    }
    __syncthreads();

    const float4* xbase = (pass == 0) ? g_xnorm : g_res;
    float2* part = (pass == 0) ? g_part1 : g_part2;

    #pragma unroll
    for (int bi = 0; bi < 4; bi++) {
        int b = bh * 32 + w * 4 + bi;
        const float4* xr = xbase + (size_t)b * D4;
        float4 q[6];
        #pragma unroll
        for (int j = 0; j < 6; j++) q[j] = xr[lane + j * 32];

        float best = -1e30f; int bp = 0;
        #pragma unroll
        for (int kr = 0; kr < KPB; kr++) {
            float s = 0.f;
            #pragma unroll
            for (int j = 0; j < 6; j++) {
                float4 k = kk[kr][lane + j * 32];
                s += q[j].x * k.x + q[j].y * k.y + q[j].z * k.z + q[j].w * k.w;
            }
            #pragma unroll
            for (int o = 16; o; o >>= 1) s += __shfl_xor_sync(0xffffffffu, s, o);
            s *= inv[kr];
            if (s > best) { best = s; bp = kb * KPB + kr; }  // ascending -> lowest idx
        }
        if (lane == 0) {
            float2 pr; pr.x = best; pr.y = __int_as_float(bp);
            part[(size_t)b * NBLK + kb] = pr;
        }
    }
}

// ---------------------------------------------------------------------------
// K4: final argmax over g_part1 (lowest-index tie-break) + residual.
// grid = BB, block = 128. (R9 version.)
// ---------------------------------------------------------------------------
__global__ __launch_bounds__(128) void final1_kernel(const float* __restrict__ pkey)
{
    int b = blockIdx.x;
    int tid = threadIdx.x;

    __shared__ float bv[128];
    __shared__ int   bp[128];

    float2 pr = g_part1[(size_t)b * NBLK + tid];
    bv[tid] = pr.x; bp[tid] = __float_as_int(pr.y);
    __syncthreads();
    for (int o = 64; o >= 1; o >>= 1) {
        if (tid < o) {
            float v = bv[tid + o]; int p = bp[tid + o];
            if (v > bv[tid] || (v == bv[tid] && p < bp[tid])) { bv[tid] = v; bp[tid] = p; }
        }
        __syncthreads();
    }
    if (tid == 0) { g_idx1[b] = bp[0]; g_m1[b] = bv[0]; }

    int id = bp[0];
    const float* kp = pkey + (size_t)id * DIM;
    const float* xn = (const float*)&g_xnorm[(size_t)b * D4];
    float* rs = (float*)&g_res[(size_t)b * D4];
    #pragma unroll
    for (int j = 0; j < DIM / 128; j++) {
        int c = tid + j * 128;
        rs[c] = kp[c] - xn[c];
    }
}

// ---------------------------------------------------------------------------
// K6: final argmax over g_part2 + fused prompt gather + scalar.
// grid = BB, block = 256. (R9 version, atomic-free scalar via fixed-order sum
// is done in final2 of R9? R9 used atomics+ticket; keep R9's exact scheme.)
// ---------------------------------------------------------------------------
__device__ float g_m2v[BB];
__device__ unsigned int g_count;

__global__ __launch_bounds__(256) void final2_kernel(
    const float4* __restrict__ prompt, const float4* __restrict__ rprompt,
    float4* __restrict__ out, int write_scalar, size_t scalar_off)
{
    int b = blockIdx.x;
    int tid = threadIdx.x;

    __shared__ float bv[128];
    __shared__ int   bp[128];

    if (tid < 128) {
        float2 pr = g_part2[(size_t)b * NBLK + tid];
        bv[tid] = pr.x; bp[tid] = __float_as_int(pr.y);
    }
    __syncthreads();
    for (int o = 64; o >= 1; o >>= 1) {
        if (tid < o) {
            float v = bv[tid + o]; int p = bp[tid + o];
            if (v > bv[tid] || (v == bv[tid] && p < bp[tid])) { bv[tid] = v; bp[tid] = p; }
        }
        __syncthreads();
    }
    int id2 = bp[0];
    int id1 = g_idx1[b];

    // fused gather: rows [0,16) = residual prompt tile, [16,32) = prompt tile
    const float4* src1 = rprompt + (size_t)id2 * PLEN * D4;
    const float4* src2 = prompt  + (size_t)id1 * PLEN * D4;
    float4* dst = out + (size_t)b * OUTROWS * D4;

    const int TOT = PLEN * D4;                 // 3072 float4 per tile
    #pragma unroll
    for (int j = 0; j < TOT / 256; j++) {      // 12 iterations
        int i = tid + j * 256;
        dst[i]       = src1[i];
        dst[TOT + i] = src2[i];
    }

    if (tid == 0) {
        g_m2v[b] = bv[0];
        __threadfence();
        unsigned int old = atomicAdd(&g_count, 1u);
        if (old == BB - 1) {
            g_count = 0u;                      // reset for graph replay
            if (write_scalar) {
                __threadfence();               // acquire peers' g_m2v stores
                float total = 0.f;
                #pragma unroll
                for (int bb = 0; bb < BB; bb++) total += g_m1[bb] + g_m2v[bb];
                ((float*)out)[scalar_off] = total * (1.0f / BB);
            }
        }
    }
}

// ---------------------------------------------------------------------------
extern "C" void kernel_launch(void* const* d_in, const int* in_sizes, int n_in,
                              void* d_out, int out_size)
{
    const float4* x       = (const float4*)d_in[0];
    const float4* prompt  = (const float4*)d_in[1];
    const float4* pkey4   = (const float4*)d_in[2];
    const float4* rprompt = (const float4*)d_in[3];
    const float4* rkey4   = (const float4*)d_in[4];
    float4* out = (float4*)d_out;

    copy_mean_kernel<<<BB * CHUNKS, D4>>>(x, out);
    xnorm_kernel<<<BB, D4>>>();
    sim_kernel<<<2 * NBLK, 256>>>(pkey4, 0);
    final1_kernel<<<BB, 128>>>((const float*)pkey4);
    sim_kernel<<<2 * NBLK, 256>>>(rkey4, 1);

    long long prompted_elems = (long long)BB * OUTROWS * DIM;  // 102,236,160
    int write_scalar = ((long long)out_size > prompted_elems) ? 1 : 0;
    final2_kernel<<<BB, 256>>>(prompt, rprompt, out, write_scalar,
                               (size_t)prompted_elems);
}

// round 14
// speedup vs baseline: 1.3215x; 1.0232x over previous
#include <cuda_runtime.h>

#define BB 64
#define NN 2048
#define DIM 768
#define D4 (DIM / 4)             // 192 float4 per row
#define POOL 1024
#define PLEN 16
#define ROWS 128                 // rows per copy/mean block
#define CHUNKS (NN / ROWS)       // 16 partial chunks per batch
#define OUTROWS (2 * PLEN + NN)  // 2080
#define KPB 8                    // keys per sim block
#define NBLK (POOL / KPB)        // 128 key-blocks
#define EPS 1e-12f

// Static device scratch — referenced ONLY from device code.
__device__ float4 g_partial[BB * CHUNKS * D4];   // 3.1 MB chunked row-sums
__device__ float4 g_xnorm[BB * D4];
__device__ float2 g_part1[BB * NBLK];            // (val, idx-bits) partial argmax
__device__ float2 g_part2[BB * NBLK];
__device__ float  g_sum[BB];                     // per-batch m1+m2 for scalar
__device__ unsigned int g_count;                 // final2 ticket (self-resetting)

// ---------------------------------------------------------------------------
// K1: stream x_embed -> out rows [32,2080) via float4, accumulating per-chunk
// column sums. grid = BB*CHUNKS (1024), block = 192. Streaming cache hints:
// src is read-once, dst is write-once -> keep them out of L2's hot set.
// ---------------------------------------------------------------------------
__global__ __launch_bounds__(D4) void copy_mean_kernel(
    const float4* __restrict__ x, float4* __restrict__ out)
{
    int blk = blockIdx.x;
    int b = blk / CHUNKS;
    int k = blk % CHUNKS;
    int c = threadIdx.x;

    const float4* src = x   + ((size_t)b * NN + (size_t)k * ROWS) * D4 + c;
    float4*       dst = out + ((size_t)b * OUTROWS + 2 * PLEN + (size_t)k * ROWS) * D4 + c;

    float4 s = make_float4(0.f, 0.f, 0.f, 0.f);
    #pragma unroll 8
    for (int r = 0; r < ROWS; r++) {
        float4 v = __ldcs(&src[(size_t)r * D4]);
        s.x += v.x; s.y += v.y; s.z += v.z; s.w += v.w;
        __stcs(&dst[(size_t)r * D4], v);
    }
    g_partial[((size_t)b * CHUNKS + k) * D4 + c] = s;
}

// ---------------------------------------------------------------------------
// K2: reduce chunked partials -> mean -> x_norm. grid = BB, block = 192.
// ---------------------------------------------------------------------------
__global__ __launch_bounds__(D4) void xnorm_kernel()
{
    int b = blockIdx.x;
    int c = threadIdx.x;

    float4 s = make_float4(0.f, 0.f, 0.f, 0.f);
    #pragma unroll
    for (int k = 0; k < CHUNKS; k++) {
        float4 v = g_partial[((size_t)b * CHUNKS + k) * D4 + c];
        s.x += v.x; s.y += v.y; s.z += v.z; s.w += v.w;
    }
    const float inv_n = 1.0f / NN;
    float4 m = make_float4(s.x * inv_n, s.y * inv_n, s.z * inv_n, s.w * inv_n);

    __shared__ float red[D4];
    red[c] = m.x * m.x + m.y * m.y + m.z * m.z + m.w * m.w;
    __syncthreads();
    if (c < 64) red[c] += red[c + 64] + red[c + 128];
    __syncthreads();
    for (int o = 32; o >= 1; o >>= 1) {
        if (c < o) red[c] += red[c + o];
        __syncthreads();
    }
    float inv = rsqrtf(fmaxf(red[0], EPS));
    g_xnorm[(size_t)b * D4 + c] = make_float4(m.x * inv, m.y * inv, m.z * inv, m.w * inv);
}

// ---------------------------------------------------------------------------
// K3: pass-0 similarity + per-block partial argmax (R9's proven shape).
// grid = NBLK (128), block = 256 (8 warps x 8 batches).
// ---------------------------------------------------------------------------
__global__ __launch_bounds__(256) void sim0_kernel(const float4* __restrict__ keys)
{
    int blk = blockIdx.x;
    int tid = threadIdx.x;
    int lane = tid & 31;
    int w = tid >> 5;

    __shared__ float4 kk[KPB][D4];     // 24 KB
    __shared__ float  inv[KPB];

    for (int i = tid; i < KPB * D4; i += 256) {
        int kr = i / D4, cc = i % D4;
        kk[kr][cc] = keys[((size_t)blk * KPB + kr) * D4 + cc];
    }
    __syncthreads();

    {
        float s = 0.f;
        #pragma unroll
        for (int j = 0; j < 6; j++) {
            float4 v = kk[w][lane + j * 32];
            s += v.x * v.x + v.y * v.y + v.z * v.z + v.w * v.w;
        }
        #pragma unroll
        for (int o = 16; o; o >>= 1) s += __shfl_xor_sync(0xffffffffu, s, o);
        if (lane == 0) inv[w] = rsqrtf(fmaxf(s, EPS));
    }
    __syncthreads();

    #pragma unroll
    for (int bi = 0; bi < 8; bi++) {
        int b = w * 8 + bi;
        const float4* xr = g_xnorm + (size_t)b * D4;
        float4 q[6];
        #pragma unroll
        for (int j = 0; j < 6; j++) q[j] = xr[lane + j * 32];

        float best = -1e30f; int bp = 0;
        #pragma unroll
        for (int kr = 0; kr < KPB; kr++) {
            float s = 0.f;
            #pragma unroll
            for (int j = 0; j < 6; j++) {
                float4 k = kk[kr][lane + j * 32];
                s += q[j].x * k.x + q[j].y * k.y + q[j].z * k.z + q[j].w * k.w;
            }
            #pragma unroll
            for (int o = 16; o; o >>= 1) s += __shfl_xor_sync(0xffffffffu, s, o);
            s *= inv[kr];
            if (s > best) { best = s; bp = blk * KPB + kr; }  // ascending -> lowest idx
        }
        if (lane == 0) {
            float2 pr; pr.x = best; pr.y = __int_as_float(bp);
            g_part1[(size_t)b * NBLK + blk] = pr;
        }
    }
}

// ---------------------------------------------------------------------------
// K4: pass-1 similarity. Prologue: each warp recomputes argmax1 (lowest-index
// tie-break) for its 8 batches from g_part1 (L2-resident, redundant across
// blocks, idempotent). Hot loop: residual query formed inline,
// q = pkey[id1] - xnorm. grid = NBLK (128), block = 256.
// ---------------------------------------------------------------------------
__global__ __launch_bounds__(256) void sim1_kernel(
    const float4* __restrict__ keys, const float4* __restrict__ pkey)
{
    int blk = blockIdx.x;
    int tid = threadIdx.x;
    int lane = tid & 31;
    int w = tid >> 5;

    __shared__ float4 kk[KPB][D4];     // 24 KB
    __shared__ float  inv[KPB];

    for (int i = tid; i < KPB * D4; i += 256) {
        int kr = i / D4, cc = i % D4;
        kk[kr][cc] = keys[((size_t)blk * KPB + kr) * D4 + cc];
    }

    // prologue: argmax1 for this warp's 8 batches (runs while kk loads settle)
    int id1w[8];
    #pragma unroll
    for (int bi = 0; bi < 8; bi++) {
        int b = w * 8 + bi;
        float best = -1e30f; int bp = 0x7fffffff;
        #pragma unroll
        for (int j = 0; j < NBLK / 32; j++) {      // ascending block index
            float2 pr = g_part1[(size_t)b * NBLK + lane + j * 32];
            float v = pr.x; int p = __float_as_int(pr.y);
            if (v > best || (v == best && p < bp)) { best = v; bp = p; }
        }
        #pragma unroll
        for (int o = 16; o; o >>= 1) {
            float v = __shfl_xor_sync(0xffffffffu, best, o);
            int   p = __shfl_xor_sync(0xffffffffu, bp, o);
            if (v > best || (v == best && p < bp)) { best = v; bp = p; }
        }
        id1w[bi] = bp;
    }
    __syncthreads();

    {
        float s = 0.f;
        #pragma unroll
        for (int j = 0; j < 6; j++) {
            float4 v = kk[w][lane + j * 32];
            s += v.x * v.x + v.y * v.y + v.z * v.z + v.w * v.w;
        }
        #pragma unroll
        for (int o = 16; o; o >>= 1) s += __shfl_xor_sync(0xffffffffu, s, o);
        if (lane == 0) inv[w] = rsqrtf(fmaxf(s, EPS));
    }
    __syncthreads();

    #pragma unroll
    for (int bi = 0; bi < 8; bi++) {
        int b = w * 8 + bi;
        const float4* kp = pkey    + (size_t)id1w[bi] * D4;
        const float4* xr = g_xnorm + (size_t)b * D4;
        float4 q[6];
        #pragma unroll
        for (int j = 0; j < 6; j++) {
            float4 kv = kp[lane + j * 32];
            float4 xv = xr[lane + j * 32];
            q[j] = make_float4(kv.x - xv.x, kv.y - xv.y, kv.z - xv.z, kv.w - xv.w);
        }

        float best = -1e30f; int bp = 0;
        #pragma unroll
        for (int kr = 0; kr < KPB; kr++) {
            float s = 0.f;
            #pragma unroll
            for (int j = 0; j < 6; j++) {
                float4 k = kk[kr][lane + j * 32];
                s += q[j].x * k.x + q[j].y * k.y + q[j].z * k.z + q[j].w * k.w;
            }
            #pragma unroll
            for (int o = 16; o; o >>= 1) s += __shfl_xor_sync(0xffffffffu, s, o);
            s *= inv[kr];
            if (s > best) { best = s; bp = blk * KPB + kr; }  // ascending -> lowest idx
        }
        if (lane == 0) {
            float2 pr; pr.x = best; pr.y = __int_as_float(bp);
            g_part2[(size_t)b * NBLK + blk] = pr;
        }
    }
}

// ---------------------------------------------------------------------------
// K5: final argmaxes over g_part1/g_part2 + fused prompt gather + scalar.
// grid = BB, block = 256.
// ---------------------------------------------------------------------------
__global__ __launch_bounds__(256) void final2_kernel(
    const float4* __restrict__ prompt, const float4* __restrict__ rprompt,
    float4* __restrict__ out, int write_scalar, size_t scalar_off)
{
    int b = blockIdx.x;
    int tid = threadIdx.x;

    __shared__ float bv[128];
    __shared__ int   bp[128];
    __shared__ float s_m1;
    __shared__ int   s_id1;

    // reduce g_part1 -> (m1, id1)
    if (tid < 128) {
        float2 pr = g_part1[(size_t)b * NBLK + tid];
        bv[tid] = pr.x; bp[tid] = __float_as_int(pr.y);
    }
    __syncthreads();
    for (int o = 64; o >= 1; o >>= 1) {
        if (tid < o) {
            float v = bv[tid + o]; int p = bp[tid + o];
            if (v > bv[tid] || (v == bv[tid] && p < bp[tid])) { bv[tid] = v; bp[tid] = p; }
        }
        __syncthreads();
    }
    if (tid == 0) { s_m1 = bv[0]; s_id1 = bp[0]; }
    __syncthreads();

    // reduce g_part2 -> (m2, id2)
    if (tid < 128) {
        float2 pr = g_part2[(size_t)b * NBLK + tid];
        bv[tid] = pr.x; bp[tid] = __float_as_int(pr.y);
    }
    __syncthreads();
    for (int o = 64; o >= 1; o >>= 1) {
        if (tid < o) {
            float v = bv[tid + o]; int p = bp[tid + o];
            if (v > bv[tid] || (v == bv[tid] && p < bp[tid])) { bv[tid] = v; bp[tid] = p; }
        }
        __syncthreads();
    }
    int id2 = bp[0];
    int id1 = s_id1;

    // fused gather: rows [0,16) = residual prompt tile, [16,32) = prompt tile
    const float4* src1 = rprompt + (size_t)id2 * PLEN * D4;
    const float4* src2 = prompt  + (size_t)id1 * PLEN * D4;
    float4* dst = out + (size_t)b * OUTROWS * D4;

    const int TOT = PLEN * D4;                 // 3072 float4 per tile
    #pragma unroll
    for (int j = 0; j < TOT / 256; j++) {      // 12 iterations
        int i = tid + j * 256;
        dst[i]       = src1[i];
        dst[TOT + i] = src2[i];
    }

    if (tid == 0) {
        g_sum[b] = s_m1 + bv[0];
        __threadfence();
        unsigned int old = atomicAdd(&g_count, 1u);
        if (old == BB - 1) {
            g_count = 0u;                      // reset for graph replay
            if (write_scalar) {
                __threadfence();               // acquire peers' g_sum stores
                float total = 0.f;
                #pragma unroll
                for (int bb = 0; bb < BB; bb++) total += g_sum[bb];
                ((float*)out)[scalar_off] = total * (1.0f / BB);
            }
        }
    }
}

// ---------------------------------------------------------------------------
extern "C" void kernel_launch(void* const* d_in, const int* in_sizes, int n_in,
                              void* d_out, int out_size)
{
    const float4* x       = (const float4*)d_in[0];
    const float4* prompt  = (const float4*)d_in[1];
    const float4* pkey4   = (const float4*)d_in[2];
    const float4* rprompt = (const float4*)d_in[3];
    const float4* rkey4   = (const float4*)d_in[4];
    float4* out = (float4*)d_out;

    copy_mean_kernel<<<BB * CHUNKS, D4>>>(x, out);
    xnorm_kernel<<<BB, D4>>>();
    sim0_kernel<<<NBLK, 256>>>(pkey4);
    sim1_kernel<<<NBLK, 256>>>(rkey4, pkey4);

    long long prompted_elems = (long long)BB * OUTROWS * DIM;  // 102,236,160
    int write_scalar = ((long long)out_size > prompted_elems) ? 1 : 0;
    final2_kernel<<<BB, 256>>>(prompt, rprompt, out, write_scalar,
                               (size_t)prompted_elems);
}

// round 15
// speedup vs baseline: 1.3344x; 1.0098x over previous
#include <cuda_runtime.h>

#define BB 64
#define NN 2048
#define DIM 768
#define D4 (DIM / 4)             // 192 float4 per row
#define POOL 1024
#define PLEN 16
#define ROWS 128                 // rows per copy/mean block
#define CHUNKS (NN / ROWS)       // 16 partial chunks per batch
#define OUTROWS (2 * PLEN + NN)  // 2080
#define KPB 8                    // keys per sim block
#define NBLK (POOL / KPB)        // 128 key-blocks
#define EPS 1e-12f

// Static device scratch — referenced ONLY from device code.
__device__ float4 g_partial[BB * CHUNKS * D4];   // 3.1 MB chunked row-sums
__device__ float4 g_xnorm[BB * D4];
__device__ float2 g_part1[BB * NBLK];            // (val, idx-bits) partial argmax
__device__ float2 g_part2[BB * NBLK];
__device__ float  g_sum[BB];                     // per-batch m1+m2 for scalar
__device__ unsigned int g_count;                 // final2 ticket (self-resetting)

// ---------------------------------------------------------------------------
// K1: stream x_embed -> out rows [32,2080) via float4, accumulating per-chunk
// column sums. grid = BB*CHUNKS (1024), block = 192. Streaming cache hints on
// the read-once/write-once copy path.
// ---------------------------------------------------------------------------
__global__ __launch_bounds__(D4) void copy_mean_kernel(
    const float4* __restrict__ x, float4* __restrict__ out)
{
    int blk = blockIdx.x;
    int b = blk / CHUNKS;
    int k = blk % CHUNKS;
    int c = threadIdx.x;

    const float4* src = x   + ((size_t)b * NN + (size_t)k * ROWS) * D4 + c;
    float4*       dst = out + ((size_t)b * OUTROWS + 2 * PLEN + (size_t)k * ROWS) * D4 + c;

    float4 s = make_float4(0.f, 0.f, 0.f, 0.f);
    #pragma unroll 8
    for (int r = 0; r < ROWS; r++) {
        float4 v = __ldcs(&src[(size_t)r * D4]);
        s.x += v.x; s.y += v.y; s.z += v.z; s.w += v.w;
        __stcs(&dst[(size_t)r * D4], v);
    }
    g_partial[((size_t)b * CHUNKS + k) * D4 + c] = s;
}

// ---------------------------------------------------------------------------
// K2: reduce chunked partials -> mean -> x_norm. grid = BB, block = 192.
// (R9-exact: sequential chunk order, fixed-order tree reduce.)
// ---------------------------------------------------------------------------
__global__ __launch_bounds__(D4) void xnorm_kernel()
{
    int b = blockIdx.x;
    int c = threadIdx.x;

    float4 s = make_float4(0.f, 0.f, 0.f, 0.f);
    #pragma unroll
    for (int k = 0; k < CHUNKS; k++) {
        float4 v = g_partial[((size_t)b * CHUNKS + k) * D4 + c];
        s.x += v.x; s.y += v.y; s.z += v.z; s.w += v.w;
    }
    const float inv_n = 1.0f / NN;
    float4 m = make_float4(s.x * inv_n, s.y * inv_n, s.z * inv_n, s.w * inv_n);

    __shared__ float red[D4];
    red[c] = m.x * m.x + m.y * m.y + m.z * m.z + m.w * m.w;
    __syncthreads();
    if (c < 64) red[c] += red[c + 64] + red[c + 128];
    __syncthreads();
    for (int o = 32; o >= 1; o >>= 1) {
        if (c < o) red[c] += red[c + o];
        __syncthreads();
    }
    float inv = rsqrtf(fmaxf(red[0], EPS));
    g_xnorm[(size_t)b * D4 + c] = make_float4(m.x * inv, m.y * inv, m.z * inv, m.w * inv);
}

// ---------------------------------------------------------------------------
// K3: pass-0 similarity + per-block partial argmax (R9's proven shape).
// grid = NBLK (128), block = 256 (8 warps x 8 batches).
// ---------------------------------------------------------------------------
__global__ __launch_bounds__(256) void sim0_kernel(const float4* __restrict__ keys)
{
    int blk = blockIdx.x;
    int tid = threadIdx.x;
    int lane = tid & 31;
    int w = tid >> 5;

    __shared__ float4 kk[KPB][D4];     // 24 KB
    __shared__ float  inv[KPB];

    for (int i = tid; i < KPB * D4; i += 256) {
        int kr = i / D4, cc = i % D4;
        kk[kr][cc] = keys[((size_t)blk * KPB + kr) * D4 + cc];
    }
    __syncthreads();

    {
        float s = 0.f;
        #pragma unroll
        for (int j = 0; j < 6; j++) {
            float4 v = kk[w][lane + j * 32];
            s += v.x * v.x + v.y * v.y + v.z * v.z + v.w * v.w;
        }
        #pragma unroll
        for (int o = 16; o; o >>= 1) s += __shfl_xor_sync(0xffffffffu, s, o);
        if (lane == 0) inv[w] = rsqrtf(fmaxf(s, EPS));
    }
    __syncthreads();

    #pragma unroll
    for (int bi = 0; bi < 8; bi++) {
        int b = w * 8 + bi;
        const float4* xr = g_xnorm + (size_t)b * D4;
        float4 q[6];
        #pragma unroll
        for (int j = 0; j < 6; j++) q[j] = xr[lane + j * 32];

        float best = -1e30f; int bp = 0;
        #pragma unroll
        for (int kr = 0; kr < KPB; kr++) {
            float s = 0.f;
            #pragma unroll
            for (int j = 0; j < 6; j++) {
                float4 k = kk[kr][lane + j * 32];
                s += q[j].x * k.x + q[j].y * k.y + q[j].z * k.z + q[j].w * k.w;
            }
            #pragma unroll
            for (int o = 16; o; o >>= 1) s += __shfl_xor_sync(0xffffffffu, s, o);
            s *= inv[kr];
            if (s > best) { best = s; bp = blk * KPB + kr; }  // ascending -> lowest idx
        }
        if (lane == 0) {
            float2 pr; pr.x = best; pr.y = __int_as_float(bp);
            g_part1[(size_t)b * NBLK + blk] = pr;
        }
    }
}

// ---------------------------------------------------------------------------
// K4: pass-1 similarity. Prologue: warps cooperatively recompute argmax1
// (lowest-index tie-break) for all 64 batches from g_part1 into SHARED MEMORY
// — only scalar best/bp live, nothing spans the hot loop. Hot loop: residual
// query formed inline (q = pkey[s_id1[b]] - xnorm). grid = NBLK, block = 256.
// ---------------------------------------------------------------------------
__global__ __launch_bounds__(256) void sim1_kernel(
    const float4* __restrict__ keys, const float4* __restrict__ pkey)
{
    int blk = blockIdx.x;
    int tid = threadIdx.x;
    int lane = tid & 31;
    int w = tid >> 5;

    __shared__ float4 kk[KPB][D4];     // 24 KB
    __shared__ float  inv[KPB];
    __shared__ int    s_id1[BB];

    for (int i = tid; i < KPB * D4; i += 256) {
        int kr = i / D4, cc = i % D4;
        kk[kr][cc] = keys[((size_t)blk * KPB + kr) * D4 + cc];
    }

    // prologue: warp w -> argmax1 for batches w*8..w*8+7, result to smem only
    for (int bi = 0; bi < 8; bi++) {
        int b = w * 8 + bi;
        float best = -1e30f; int bp = 0x7fffffff;
        for (int j = 0; j < NBLK / 32; j++) {      // ascending block index
            float2 pr = g_part1[(size_t)b * NBLK + lane + j * 32];
            float v = pr.x; int p = __float_as_int(pr.y);
            if (v > best || (v == best && p < bp)) { best = v; bp = p; }
        }
        #pragma unroll
        for (int o = 16; o; o >>= 1) {
            float v = __shfl_xor_sync(0xffffffffu, best, o);
            int   p = __shfl_xor_sync(0xffffffffu, bp, o);
            if (v > best || (v == best && p < bp)) { best = v; bp = p; }
        }
        if (lane == 0) s_id1[b] = bp;
    }
    __syncthreads();

    {
        float s = 0.f;
        #pragma unroll
        for (int j = 0; j < 6; j++) {
            float4 v = kk[w][lane + j * 32];
            s += v.x * v.x + v.y * v.y + v.z * v.z + v.w * v.w;
        }
        #pragma unroll
        for (int o = 16; o; o >>= 1) s += __shfl_xor_sync(0xffffffffu, s, o);
        if (lane == 0) inv[w] = rsqrtf(fmaxf(s, EPS));
    }
    __syncthreads();

    #pragma unroll
    for (int bi = 0; bi < 8; bi++) {
        int b = w * 8 + bi;
        const float4* kp = pkey    + (size_t)s_id1[b] * D4;
        const float4* xr = g_xnorm + (size_t)b * D4;
        float4 q[6];
        #pragma unroll
        for (int j = 0; j < 6; j++) {
            float4 kv = kp[lane + j * 32];
            float4 xv = xr[lane + j * 32];
            q[j] = make_float4(kv.x - xv.x, kv.y - xv.y, kv.z - xv.z, kv.w - xv.w);
        }

        float best = -1e30f; int bp = 0;
        #pragma unroll
        for (int kr = 0; kr < KPB; kr++) {
            float s = 0.f;
            #pragma unroll
            for (int j = 0; j < 6; j++) {
                float4 k = kk[kr][lane + j * 32];
                s += q[j].x * k.x + q[j].y * k.y + q[j].z * k.z + q[j].w * k.w;
            }
            #pragma unroll
            for (int o = 16; o; o >>= 1) s += __shfl_xor_sync(0xffffffffu, s, o);
            s *= inv[kr];
            if (s > best) { best = s; bp = blk * KPB + kr; }  // ascending -> lowest idx
        }
        if (lane == 0) {
            float2 pr; pr.x = best; pr.y = __int_as_float(bp);
            g_part2[(size_t)b * NBLK + blk] = pr;
        }
    }
}

// ---------------------------------------------------------------------------
// K5: final argmaxes over g_part1/g_part2 + fused prompt gather + scalar.
// grid = BB, block = 256.
// ---------------------------------------------------------------------------
__global__ __launch_bounds__(256) void final2_kernel(
    const float4* __restrict__ prompt, const float4* __restrict__ rprompt,
    float4* __restrict__ out, int write_scalar, size_t scalar_off)
{
    int b = blockIdx.x;
    int tid = threadIdx.x;

    __shared__ float bv[128];
    __shared__ int   bp[128];
    __shared__ float s_m1;
    __shared__ int   s_id1;

    // reduce g_part1 -> (m1, id1)
    if (tid < 128) {
        float2 pr = g_part1[(size_t)b * NBLK + tid];
        bv[tid] = pr.x; bp[tid] = __float_as_int(pr.y);
    }
    __syncthreads();
    for (int o = 64; o >= 1; o >>= 1) {
        if (tid < o) {
            float v = bv[tid + o]; int p = bp[tid + o];
            if (v > bv[tid] || (v == bv[tid] && p < bp[tid])) { bv[tid] = v; bp[tid] = p; }
        }
        __syncthreads();
    }
    if (tid == 0) { s_m1 = bv[0]; s_id1 = bp[0]; }
    __syncthreads();

    // reduce g_part2 -> (m2, id2)
    if (tid < 128) {
        float2 pr = g_part2[(size_t)b * NBLK + tid];
        bv[tid] = pr.x; bp[tid] = __float_as_int(pr.y);
    }
    __syncthreads();
    for (int o = 64; o >= 1; o >>= 1) {
        if (tid < o) {
            float v = bv[tid + o]; int p = bp[tid + o];
            if (v > bv[tid] || (v == bv[tid] && p < bp[tid])) { bv[tid] = v; bp[tid] = p; }
        }
        __syncthreads();
    }
    int id2 = bp[0];
    int id1 = s_id1;

    // fused gather: rows [0,16) = residual prompt tile, [16,32) = prompt tile
    const float4* src1 = rprompt + (size_t)id2 * PLEN * D4;
    const float4* src2 = prompt  + (size_t)id1 * PLEN * D4;
    float4* dst = out + (size_t)b * OUTROWS * D4;

    const int TOT = PLEN * D4;                 // 3072 float4 per tile
    #pragma unroll
    for (int j = 0; j < TOT / 256; j++) {      // 12 iterations
        int i = tid + j * 256;
        dst[i]       = src1[i];
        dst[TOT + i] = src2[i];
    }

    if (tid == 0) {
        g_sum[b] = s_m1 + bv[0];
        __threadfence();
        unsigned int old = atomicAdd(&g_count, 1u);
        if (old == BB - 1) {
            g_count = 0u;                      // reset for graph replay
            if (write_scalar) {
                __threadfence();               // acquire peers' g_sum stores
                float total = 0.f;
                #pragma unroll
                for (int bb = 0; bb < BB; bb++) total += g_sum[bb];
                ((float*)out)[scalar_off] = total * (1.0f / BB);
            }
        }
    }
}

// ---------------------------------------------------------------------------
extern "C" void kernel_launch(void* const* d_in, const int* in_sizes, int n_in,
                              void* d_out, int out_size)
{
    const float4* x       = (const float4*)d_in[0];
    const float4* prompt  = (const float4*)d_in[1];
    const float4* pkey4   = (const float4*)d_in[2];
    const float4* rprompt = (const float4*)d_in[3];
    const float4* rkey4   = (const float4*)d_in[4];
    float4* out = (float4*)d_out;

    copy_mean_kernel<<<BB * CHUNKS, D4>>>(x, out);
    xnorm_kernel<<<BB, D4>>>();
    sim0_kernel<<<NBLK, 256>>>(pkey4);
    sim1_kernel<<<NBLK, 256>>>(rkey4, pkey4);

    long long prompted_elems = (long long)BB * OUTROWS * DIM;  // 102,236,160
    int write_scalar = ((long long)out_size > prompted_elems) ? 1 : 0;
    final2_kernel<<<BB, 256>>>(prompt, rprompt, out, write_scalar,
                               (size_t)prompted_elems);
}